// round 7
// baseline (speedup 1.0000x reference)
#include <cuda_runtime.h>

#define N_USERS 50000
#define N_ENT   150000
#define NN      200000
#define NE      2000000
#define NB      8192
#define TOT     176   // 64 + 64 + 32 + 16
#define NCHUNK  256
#define CHSZ    782   // ceil(NN/256)

// Scratch (allocation-free rule: __device__ globals)
__device__ float g_ego [NN * 64];
__device__ float g_ego2[NN * 64];
__device__ float g_all [NN * TOT];
__device__ int   g_deg   [NN];
__device__ int   g_off   [NN];     // working copy of rowptr for placement
__device__ int   g_rowptr[NN];
__device__ int   g_csum  [NCHUNK];
__device__ int   g_coff  [NCHUNK];
__device__ int2  g_edge  [NE];      // (col, bitcast(val)) grouped by row

// ---------------------------------------------------------------------------
// packed f32x2 helpers (FFMA2 only reachable via PTX)
__device__ __forceinline__ unsigned long long pk2(float a) {
    unsigned long long r;
    asm("mov.b64 %0, {%1, %1};" : "=l"(r) : "f"(a));
    return r;
}
__device__ __forceinline__ void ffma2(unsigned long long& d,
                                      unsigned long long a, unsigned long long b) {
    asm("fma.rn.f32x2 %0, %1, %2, %0;" : "+l"(d) : "l"(a), "l"(b));
}
__device__ __forceinline__ float2 upk2(unsigned long long v) {
    float x, y;
    asm("mov.b64 {%0, %1}, %2;" : "=f"(x), "=f"(y) : "l"(v));
    return make_float2(x, y);
}

// ---------------------------------------------------------------------------
__global__ void k_init(const float* __restrict__ ue, const float* __restrict__ ee) {
    int i = blockIdx.x * blockDim.x + threadIdx.x;   // over NN*16
    if (i >= NN * 16) return;
    int n = i >> 4, c = i & 15;
    float4 v = (n < N_USERS)
        ? ((const float4*)ue)[(size_t)n * 16 + c]
        : ((const float4*)ee)[(size_t)(n - N_USERS) * 16 + c];
    ((float4*)g_ego)[i] = v;
    ((float4*)(g_all + (size_t)n * TOT))[c] = v;
}

__global__ void k_zero1(int* __restrict__ a, int n) {
    int i = blockIdx.x * blockDim.x + threadIdx.x;
    if (i < n) a[i] = 0;
}

// ---------------------------------------------------------------------------
// CSR build
__global__ void k_hist(const int* __restrict__ rows) {
    int e = blockIdx.x * blockDim.x + threadIdx.x;
    if (e < NE) atomicAdd(&g_deg[rows[e]], 1);
}

__global__ void k_csum() {  // 256 blocks x 256 threads: chunk sums
    __shared__ int s[256];
    int b = blockIdx.x, tid = threadIdx.x;
    int beg = b * CHSZ, end = min(beg + CHSZ, NN);
    int acc = 0;
    for (int i = beg + tid; i < end; i += 256) acc += g_deg[i];
    s[tid] = acc; __syncthreads();
    for (int o = 128; o > 0; o >>= 1) { if (tid < o) s[tid] += s[tid + o]; __syncthreads(); }
    if (tid == 0) g_csum[b] = s[0];
}

__global__ void k_scan256() {  // 1 block: exclusive scan of chunk sums
    __shared__ int s[256];
    int tid = threadIdx.x;
    int v = g_csum[tid];
    s[tid] = v; __syncthreads();
    for (int o = 1; o < 256; o <<= 1) {
        int t = (tid >= o) ? s[tid - o] : 0;
        __syncthreads(); s[tid] += t; __syncthreads();
    }
    g_coff[tid] = s[tid] - v;
}

__global__ void k_rowptr() {  // 256 blocks: scan within chunk; writes rowptr + working copy
    __shared__ int s[256];
    __shared__ int stot;
    int b = blockIdx.x, tid = threadIdx.x;
    int beg = b * CHSZ, end = min(beg + CHSZ, NN);
    int running = g_coff[b];
    for (int t = beg; t < end; t += 256) {
        int idx = t + tid;
        int v = (idx < end) ? g_deg[idx] : 0;
        s[tid] = v; __syncthreads();
        for (int o = 1; o < 256; o <<= 1) {
            int u = (tid >= o) ? s[tid - o] : 0;
            __syncthreads(); s[tid] += u; __syncthreads();
        }
        if (idx < end) {
            int rp = running + s[tid] - v;
            g_rowptr[idx] = rp;
            g_off[idx]    = rp;
        }
        if (tid == 255) stot = s[255];
        __syncthreads();
        running += stot;
        __syncthreads();
    }
}

__global__ void k_place(const int* __restrict__ rows, const int* __restrict__ cols,
                        const float* __restrict__ vals) {
    int e = blockIdx.x * blockDim.x + threadIdx.x;
    if (e >= NE) return;
    int r = rows[e];
    int p = atomicAdd(&g_off[r], 1);
    g_edge[p] = make_int2(cols[e], __float_as_int(vals[e]));
}

// ---------------------------------------------------------------------------
// Fused: side-gather + GC/BI transform + l2norm.
// Gather: warp per node, edge headers loaded once per 32-block, broadcast by
// shfl; inner loop padded to a multiple of 4 and unrolled with 4 independent
// accumulator sets (8 LDGs in flight, fma chain broken 4-way). Padded lanes
// carry ev=(0,0): they read row 0 (L1-hot) and add 0 — harmless.
// Matmul: node-tiled (NT=4) + packed FFMA2.
template<int DIN, int DOUT, int OFF>
__global__ void k_layer(const float* __restrict__ Wg, const float* __restrict__ bg,
                        const float* __restrict__ Wb, const float* __restrict__ bb,
                        const float* __restrict__ src, float* __restrict__ dst) {
    constexpr int KC  = DIN / 32;
    constexpr int LPM = DOUT / 4;       // active lanes per matrix
    constexpr int NT  = 4;              // nodes per warp per matmul pass
    constexpr int WPB = 6;
    __shared__ __align__(16) float sW[2 * DIN * DOUT];
    __shared__ __align__(16) float sB[2 * DOUT];
    __shared__ __align__(16) float sx[WPB][NT][2][DIN];

    int tid = threadIdx.x;
    for (int i = tid; i < DIN * DOUT; i += blockDim.x) { sW[i] = Wg[i]; sW[DIN * DOUT + i] = Wb[i]; }
    for (int i = tid; i < DOUT; i += blockDim.x)       { sB[i] = bg[i]; sB[DOUT + i] = bb[i]; }
    __syncthreads();

    int w = tid >> 5, lane = tid & 31;
    int h  = lane >> 4;                 // 0 = GC, 1 = BI
    int jl = lane & 15;
    int jc = (jl < LPM) ? jl : 0;
    const float* wbase = sW + h * DIN * DOUT;

    for (int nb = (blockIdx.x * WPB + w) * NT; nb < NN; nb += gridDim.x * WPB * NT) {
        // ---- gather NT nodes into sx ----
        #pragma unroll
        for (int t = 0; t < NT; t++) {
            int n = nb + t;
            if (n >= NN) break;
            float er[KC];
            float au[4][KC];
            #pragma unroll
            for (int c = 0; c < KC; c++) {
                er[c] = src[(size_t)n * DIN + lane + 32 * c];
                #pragma unroll
                for (int u = 0; u < 4; u++) au[u][c] = 0.f;
            }
            int s0 = g_rowptr[n], cnt = g_deg[n];
            for (int base = 0; base < cnt; base += 32) {
                int2 ev = make_int2(0, 0);
                if (base + lane < cnt) ev = g_edge[s0 + base + lane];
                int vn4 = (min(32, cnt - base) + 3) & ~3;
                for (int m = 0; m < vn4; m += 4) {
                    #pragma unroll
                    for (int u = 0; u < 4; u++) {
                        int   col = __shfl_sync(0xffffffffu, ev.x, m + u);
                        float val = __int_as_float(__shfl_sync(0xffffffffu, ev.y, m + u));
                        #pragma unroll
                        for (int c = 0; c < KC; c++)
                            au[u][c] = fmaf(val, src[(size_t)col * DIN + lane + 32 * c], au[u][c]);
                    }
                }
            }
            #pragma unroll
            for (int c = 0; c < KC; c++) {
                float acc = (au[0][c] + au[1][c]) + (au[2][c] + au[3][c]);
                int k = lane + 32 * c;
                sx[w][t][0][k] = er[c] + acc;
                sx[w][t][1][k] = er[c] * acc;
            }
        }
        __syncwarp();

        // ---- node-tiled matmul with packed FFMA2 ----
        unsigned long long p01[NT], p23[NT];
        #pragma unroll
        for (int t = 0; t < NT; t++) { p01[t] = 0ull; p23[t] = 0ull; }

        #pragma unroll
        for (int k4 = 0; k4 < DIN; k4 += 4) {
            float4 xv[NT];
            #pragma unroll
            for (int t = 0; t < NT; t++)
                xv[t] = *(const float4*)(&sx[w][t][h][k4]);
            #pragma unroll
            for (int i = 0; i < 4; i++) {
                ulonglong2 wv = ((const ulonglong2*)(wbase + (k4 + i) * DOUT))[jc];
                #pragma unroll
                for (int t = 0; t < NT; t++) {
                    unsigned long long xx = pk2((&xv[t].x)[i]);
                    ffma2(p01[t], xx, wv.x);
                    ffma2(p23[t], xx, wv.y);
                }
            }
        }

        float4 bv = ((const float4*)(sB + h * DOUT))[jc];
        #pragma unroll
        for (int t = 0; t < NT; t++) {
            int n = nb + t;
            float2 a01 = upk2(p01[t]), a23 = upk2(p23[t]);
            float4 v;
            v.x = a01.x + bv.x; v.x = v.x > 0.f ? v.x : 0.01f * v.x;
            v.y = a01.y + bv.y; v.y = v.y > 0.f ? v.y : 0.01f * v.y;
            v.z = a23.x + bv.z; v.z = v.z > 0.f ? v.z : 0.01f * v.z;
            v.w = a23.y + bv.w; v.w = v.w > 0.f ? v.w : 0.01f * v.w;
            float4 o;
            o.x = v.x + __shfl_xor_sync(0xffffffffu, v.x, 16);
            o.y = v.y + __shfl_xor_sync(0xffffffffu, v.y, 16);
            o.z = v.z + __shfl_xor_sync(0xffffffffu, v.z, 16);
            o.w = v.w + __shfl_xor_sync(0xffffffffu, v.w, 16);
            float ss = o.x * o.x + o.y * o.y + o.z * o.z + o.w * o.w;
            #pragma unroll
            for (int off = LPM / 2; off > 0; off >>= 1)
                ss += __shfl_xor_sync(0xffffffffu, ss, off);
            float inv = 1.0f / fmaxf(sqrtf(ss), 1e-12f);
            if (n < NN && h == 0 && jl < LPM) {
                ((float4*)(dst + (size_t)n * DOUT))[jl] = o;
                float4 on = make_float4(o.x * inv, o.y * inv, o.z * inv, o.w * inv);
                ((float4*)(g_all + (size_t)n * TOT + OFF))[jl] = on;
            }
        }
        __syncwarp();
    }
}

// ---------------------------------------------------------------------------
__global__ void k_score(const int* __restrict__ users, const int* __restrict__ pos,
                        const int* __restrict__ neg, float* __restrict__ out) {
    int wid  = (blockIdx.x * blockDim.x + threadIdx.x) >> 5;
    int lane = threadIdx.x & 31;
    if (wid >= NB) return;
    const float* u = g_all + (size_t)users[wid] * TOT;
    const float* p = g_all + (size_t)(N_USERS + pos[wid]) * TOT;
    const float* q = g_all + (size_t)(N_USERS + neg[wid]) * TOT;
    float sp = 0.f, sn = 0.f;
    #pragma unroll
    for (int k = lane; k < TOT; k += 32) {
        float uv = u[k];
        sp += uv * p[k];
        sn += uv * q[k];
    }
    #pragma unroll
    for (int o = 16; o > 0; o >>= 1) {
        sp += __shfl_xor_sync(0xffffffffu, sp, o);
        sn += __shfl_xor_sync(0xffffffffu, sn, o);
    }
    if (lane == 0) { out[2 * wid] = sp; out[2 * wid + 1] = sn; }
}

// ---------------------------------------------------------------------------
extern "C" void kernel_launch(void* const* d_in, const int* in_sizes, int n_in,
                              void* d_out, int out_size) {
    const int*   users = (const int*)  d_in[0];
    const int*   pos   = (const int*)  d_in[1];
    const int*   neg   = (const int*)  d_in[2];
    const int*   rows  = (const int*)  d_in[3];
    const int*   cols  = (const int*)  d_in[4];
    const float* vals  = (const float*)d_in[5];
    const float* ue    = (const float*)d_in[6];
    const float* ee    = (const float*)d_in[7];
    const float* W[3][4];
    for (int l = 0; l < 3; l++)
        for (int j = 0; j < 4; j++)
            W[l][j] = (const float*)d_in[8 + 4 * l + j];

    float *p_ego, *p_ego2;
    int *p_deg;
    cudaGetSymbolAddress((void**)&p_ego,  g_ego);
    cudaGetSymbolAddress((void**)&p_ego2, g_ego2);
    cudaGetSymbolAddress((void**)&p_deg,  g_deg);

    const int TB = 256;
    const int TBL = 192;   // 6 warps per block for k_layer

    k_init<<<(NN * 16 + TB - 1) / TB, TB>>>(ue, ee);

    // CSR build
    k_zero1<<<(NN + TB - 1) / TB, TB>>>(p_deg, NN);
    k_hist<<<(NE + TB - 1) / TB, TB>>>(rows);
    k_csum<<<NCHUNK, 256>>>();
    k_scan256<<<1, 256>>>();
    k_rowptr<<<NCHUNK, 256>>>();
    k_place<<<(NE + TB - 1) / TB, TB>>>(rows, cols, vals);

    // Layers (fused gather + node-tiled transform + l2norm)
    k_layer<64, 64,  64><<<740, TBL>>>(W[0][0], W[0][1], W[0][2], W[0][3], p_ego,  p_ego2);
    k_layer<64, 32, 128><<<740, TBL>>>(W[1][0], W[1][1], W[1][2], W[1][3], p_ego2, p_ego);
    k_layer<32, 16, 160><<<740, TBL>>>(W[2][0], W[2][1], W[2][2], W[2][3], p_ego,  p_ego2);

    k_score<<<(NB * 32 + TB - 1) / TB, TB>>>(users, pos, neg, (float*)d_out);
}

// round 9
// speedup vs baseline: 1.0594x; 1.0594x over previous
#include <cuda_runtime.h>

#define N_USERS 50000
#define N_ENT   150000
#define NN      200000
#define NE      2000000
#define NB      8192
#define TOT     176   // 64 + 64 + 32 + 16

// Scratch (allocation-free rule: __device__ globals; zero-initialized at load)
__device__ float g_ego [NN * 64];
__device__ float g_ego2[NN * 64];
__device__ float g_all [NN * TOT];
__device__ int   g_deg   [NN];
__device__ int   g_off   [NN];     // working copy of rowptr for placement
__device__ int   g_rowptr[NN];
__device__ int   g_total;
__device__ int2  g_edge  [NE];     // (col, bitcast(val)) grouped by row

// ---------------------------------------------------------------------------
// packed f32x2 helpers (FFMA2 only reachable via PTX)
__device__ __forceinline__ unsigned long long pk2(float a) {
    unsigned long long r;
    asm("mov.b64 %0, {%1, %1};" : "=l"(r) : "f"(a));
    return r;
}
__device__ __forceinline__ void ffma2(unsigned long long& d,
                                      unsigned long long a, unsigned long long b) {
    asm("fma.rn.f32x2 %0, %1, %2, %0;" : "+l"(d) : "l"(a), "l"(b));
}
__device__ __forceinline__ float2 upk2(unsigned long long v) {
    float x, y;
    asm("mov.b64 {%0, %1}, %2;" : "=f"(x), "=f"(y) : "l"(v));
    return make_float2(x, y);
}

// ---------------------------------------------------------------------------
// Launch 0: ego/all init  +  degree histogram (g_deg zeroed by previous call's
// k_score; zero-initialized for the very first call).
__global__ void k_init_hist(const float* __restrict__ ue, const float* __restrict__ ee,
                            const int* __restrict__ rows) {
    int i = blockIdx.x * blockDim.x + threadIdx.x;   // over NN*16 = 3.2M
    if (i < NN * 16) {
        int n = i >> 4, c = i & 15;
        float4 v = (n < N_USERS)
            ? ((const float4*)ue)[(size_t)n * 16 + c]
            : ((const float4*)ee)[(size_t)(n - N_USERS) * 16 + c];
        ((float4*)g_ego)[i] = v;
        ((float4*)(g_all + (size_t)n * TOT))[c] = v;
    }
    if (i < NE) atomicAdd(&g_deg[rows[i]], 1);
}

// Launch 1: rowptr by atomic allocation (order-free; rows only need contiguity)
__global__ void k_alloc() {
    int n = blockIdx.x * blockDim.x + threadIdx.x;
    if (n >= NN) return;
    int d  = g_deg[n];
    int rp = atomicAdd(&g_total, d);
    g_rowptr[n] = rp;
    g_off[n]    = rp;
}

// Launch 2: scatter edges into CSR slots
__global__ void k_place(const int* __restrict__ rows, const int* __restrict__ cols,
                        const float* __restrict__ vals) {
    int e = blockIdx.x * blockDim.x + threadIdx.x;
    if (e >= NE) return;
    int r = rows[e];
    int p = atomicAdd(&g_off[r], 1);
    g_edge[p] = make_int2(cols[e], __float_as_int(vals[e]));
}

// ---------------------------------------------------------------------------
// Launches 3-5: fused side-gather + GC/BI transform + l2norm.
// Gather: warp per node; each lane owns VE=DIN/32 contiguous elements (one
// vector LDG per edge); edge headers double-buffered (prefetch next 32-block);
// 2-way unrolled body with padded (0,0) edges (read row 0, add 0 — harmless).
// Matmul: node-tiled (NT=4) + packed FFMA2; lanes 0-15 GC, 16-31 BI.
template<int DIN, int DOUT, int OFF>
__global__ void k_layer(const float* __restrict__ Wg, const float* __restrict__ bg,
                        const float* __restrict__ Wb, const float* __restrict__ bb,
                        const float* __restrict__ src, float* __restrict__ dst) {
    constexpr int VE  = DIN / 32;       // floats per lane (2 or 1)
    constexpr int LPM = DOUT / 4;       // active lanes per matrix
    constexpr int NT  = 4;              // nodes per warp per matmul pass
    constexpr int WPB = 6;
    __shared__ __align__(16) float sW[2 * DIN * DOUT];
    __shared__ __align__(16) float sB[2 * DOUT];
    __shared__ __align__(16) float sx[WPB][NT][2][DIN];

    int tid = threadIdx.x;
    for (int i = tid; i < DIN * DOUT; i += blockDim.x) { sW[i] = Wg[i]; sW[DIN * DOUT + i] = Wb[i]; }
    for (int i = tid; i < DOUT; i += blockDim.x)       { sB[i] = bg[i]; sB[DOUT + i] = bb[i]; }
    __syncthreads();

    int w = tid >> 5, lane = tid & 31;
    int h  = lane >> 4;                 // 0 = GC, 1 = BI
    int jl = lane & 15;
    int jc = (jl < LPM) ? jl : 0;
    const float* wbase = sW + h * DIN * DOUT;

    for (int nb = (blockIdx.x * WPB + w) * NT; nb < NN; nb += gridDim.x * WPB * NT) {
        // ---- gather NT nodes into sx ----
        #pragma unroll
        for (int t = 0; t < NT; t++) {
            int n = nb + t;
            if (n >= NN) break;
            float er[VE], a0[VE], a1[VE];
            #pragma unroll
            for (int c = 0; c < VE; c++) {
                er[c] = src[(size_t)n * DIN + VE * lane + c];
                a0[c] = 0.f; a1[c] = 0.f;
            }
            int s0 = g_rowptr[n], cnt = g_deg[n];
            int2 ev = make_int2(0, 0);
            if (lane < cnt) ev = g_edge[s0 + lane];
            for (int base = 0; base < cnt; base += 32) {
                int2 evn = make_int2(0, 0);
                int nx = base + 32 + lane;
                if (nx < cnt) evn = g_edge[s0 + nx];
                int vn2 = (min(32, cnt - base) + 1) & ~1;
                for (int m = 0; m < vn2; m += 2) {
                    int   c0 = __shfl_sync(0xffffffffu, ev.x, m);
                    float v0 = __int_as_float(__shfl_sync(0xffffffffu, ev.y, m));
                    int   c1 = __shfl_sync(0xffffffffu, ev.x, m + 1);
                    float v1 = __int_as_float(__shfl_sync(0xffffffffu, ev.y, m + 1));
                    const float* r0 = src + (size_t)c0 * DIN + VE * lane;
                    const float* r1 = src + (size_t)c1 * DIN + VE * lane;
                    if (VE == 2) {
                        float2 x0 = *(const float2*)r0;
                        float2 x1 = *(const float2*)r1;
                        a0[0] = fmaf(v0, x0.x, a0[0]);
                        a0[1] = fmaf(v0, x0.y, a0[1]);
                        a1[0] = fmaf(v1, x1.x, a1[0]);
                        a1[1] = fmaf(v1, x1.y, a1[1]);
                    } else {
                        a0[0] = fmaf(v0, r0[0], a0[0]);
                        a1[0] = fmaf(v1, r1[0], a1[0]);
                    }
                }
                ev = evn;
            }
            #pragma unroll
            for (int c = 0; c < VE; c++) {
                float acc = a0[c] + a1[c];
                int k = VE * lane + c;
                sx[w][t][0][k] = er[c] + acc;
                sx[w][t][1][k] = er[c] * acc;
            }
        }
        __syncwarp();

        // ---- node-tiled matmul with packed FFMA2 ----
        unsigned long long p01[NT], p23[NT];
        #pragma unroll
        for (int t = 0; t < NT; t++) { p01[t] = 0ull; p23[t] = 0ull; }

        #pragma unroll
        for (int k4 = 0; k4 < DIN; k4 += 4) {
            float4 xv[NT];
            #pragma unroll
            for (int t = 0; t < NT; t++)
                xv[t] = *(const float4*)(&sx[w][t][h][k4]);
            #pragma unroll
            for (int i = 0; i < 4; i++) {
                ulonglong2 wv = ((const ulonglong2*)(wbase + (k4 + i) * DOUT))[jc];
                #pragma unroll
                for (int t = 0; t < NT; t++) {
                    unsigned long long xx = pk2((&xv[t].x)[i]);
                    ffma2(p01[t], xx, wv.x);
                    ffma2(p23[t], xx, wv.y);
                }
            }
        }

        float4 bv = ((const float4*)(sB + h * DOUT))[jc];
        #pragma unroll
        for (int t = 0; t < NT; t++) {
            int n = nb + t;
            float2 a01 = upk2(p01[t]), a23 = upk2(p23[t]);
            float4 v;
            v.x = a01.x + bv.x; v.x = v.x > 0.f ? v.x : 0.01f * v.x;
            v.y = a01.y + bv.y; v.y = v.y > 0.f ? v.y : 0.01f * v.y;
            v.z = a23.x + bv.z; v.z = v.z > 0.f ? v.z : 0.01f * v.z;
            v.w = a23.y + bv.w; v.w = v.w > 0.f ? v.w : 0.01f * v.w;
            float4 o;
            o.x = v.x + __shfl_xor_sync(0xffffffffu, v.x, 16);
            o.y = v.y + __shfl_xor_sync(0xffffffffu, v.y, 16);
            o.z = v.z + __shfl_xor_sync(0xffffffffu, v.z, 16);
            o.w = v.w + __shfl_xor_sync(0xffffffffu, v.w, 16);
            float ss = o.x * o.x + o.y * o.y + o.z * o.z + o.w * o.w;
            #pragma unroll
            for (int off = LPM / 2; off > 0; off >>= 1)
                ss += __shfl_xor_sync(0xffffffffu, ss, off);
            float inv = 1.0f / fmaxf(sqrtf(ss), 1e-12f);
            if (n < NN && h == 0 && jl < LPM) {
                ((float4*)(dst + (size_t)n * DOUT))[jl] = o;
                float4 on = make_float4(o.x * inv, o.y * inv, o.z * inv, o.w * inv);
                ((float4*)(g_all + (size_t)n * TOT + OFF))[jl] = on;
            }
        }
        __syncwarp();
    }
}

// ---------------------------------------------------------------------------
// Launch 6: scoring + reset g_deg/g_total for the next call (grid covers NN).
__global__ void k_score(const int* __restrict__ users, const int* __restrict__ pos,
                        const int* __restrict__ neg, float* __restrict__ out) {
    int gi = blockIdx.x * blockDim.x + threadIdx.x;
    if (gi < NN) g_deg[gi] = 0;
    if (gi == 0) g_total = 0;

    int wid  = gi >> 5;
    int lane = threadIdx.x & 31;
    if (wid >= NB) return;
    const float* u = g_all + (size_t)users[wid] * TOT;
    const float* p = g_all + (size_t)(N_USERS + pos[wid]) * TOT;
    const float* q = g_all + (size_t)(N_USERS + neg[wid]) * TOT;
    float sp = 0.f, sn = 0.f;
    #pragma unroll
    for (int k = lane; k < TOT; k += 32) {
        float uv = u[k];
        sp += uv * p[k];
        sn += uv * q[k];
    }
    #pragma unroll
    for (int o = 16; o > 0; o >>= 1) {
        sp += __shfl_xor_sync(0xffffffffu, sp, o);
        sn += __shfl_xor_sync(0xffffffffu, sn, o);
    }
    if (lane == 0) { out[2 * wid] = sp; out[2 * wid + 1] = sn; }
}

// ---------------------------------------------------------------------------
extern "C" void kernel_launch(void* const* d_in, const int* in_sizes, int n_in,
                              void* d_out, int out_size) {
    const int*   users = (const int*)  d_in[0];
    const int*   pos   = (const int*)  d_in[1];
    const int*   neg   = (const int*)  d_in[2];
    const int*   rows  = (const int*)  d_in[3];
    const int*   cols  = (const int*)  d_in[4];
    const float* vals  = (const float*)d_in[5];
    const float* ue    = (const float*)d_in[6];
    const float* ee    = (const float*)d_in[7];
    const float* W[3][4];
    for (int l = 0; l < 3; l++)
        for (int j = 0; j < 4; j++)
            W[l][j] = (const float*)d_in[8 + 4 * l + j];

    float *p_ego, *p_ego2;
    cudaGetSymbolAddress((void**)&p_ego,  g_ego);
    cudaGetSymbolAddress((void**)&p_ego2, g_ego2);

    const int TB  = 256;
    const int TBL = 192;   // 6 warps per block for k_layer

    // 0: init + histogram
    k_init_hist<<<(NN * 16 + TB - 1) / TB, TB>>>(ue, ee, rows);
    // 1: rowptr by atomic allocation
    k_alloc<<<(NN + TB - 1) / TB, TB>>>();
    // 2: CSR placement
    k_place<<<(NE + TB - 1) / TB, TB>>>(rows, cols, vals);

    // 3-5: fused layers  (launch index 3 = ncu capture slot)
    k_layer<64, 64,  64><<<740, TBL>>>(W[0][0], W[0][1], W[0][2], W[0][3], p_ego,  p_ego2);
    k_layer<64, 32, 128><<<740, TBL>>>(W[1][0], W[1][1], W[1][2], W[1][3], p_ego2, p_ego);
    k_layer<32, 16, 160><<<740, TBL>>>(W[2][0], W[2][1], W[2][2], W[2][3], p_ego,  p_ego2);

    // 6: score + scratch reset
    k_score<<<(NB * 32 + TB - 1) / TB, TB>>>(users, pos, neg, (float*)d_out);
}

// round 10
// speedup vs baseline: 1.1482x; 1.0838x over previous
#include <cuda_runtime.h>

#define N_USERS 50000
#define N_ENT   150000
#define NN      200000
#define NE      2000000
#define NB      8192
#define TOT     176   // 64 + 64 + 32 + 16

// Scratch (allocation-free rule: __device__ globals; zero-initialized at load)
__device__ float g_ego [NN * 64];
__device__ float g_ego2[NN * 64];
__device__ float g_all [NN * TOT];
__device__ int   g_deg   [NN];
__device__ int   g_off   [NN];     // working copy of rowptr for placement
__device__ int   g_rowptr[NN];
__device__ int   g_total;
__device__ int2  g_edge  [NE];     // (col, bitcast(val)) grouped by row

// ---------------------------------------------------------------------------
// packed f32x2 helpers (FFMA2 only reachable via PTX)
__device__ __forceinline__ unsigned long long pk2(float a) {
    unsigned long long r;
    asm("mov.b64 %0, {%1, %1};" : "=l"(r) : "f"(a));
    return r;
}
__device__ __forceinline__ void ffma2(unsigned long long& d,
                                      unsigned long long a, unsigned long long b) {
    asm("fma.rn.f32x2 %0, %1, %2, %0;" : "+l"(d) : "l"(a), "l"(b));
}
__device__ __forceinline__ float2 upk2(unsigned long long v) {
    float x, y;
    asm("mov.b64 {%0, %1}, %2;" : "=f"(x), "=f"(y) : "l"(v));
    return make_float2(x, y);
}

// ---------------------------------------------------------------------------
// Launch 0: ego/all init  +  degree histogram (g_deg zeroed by previous call's
// k_score; zero-initialized for the very first call).
__global__ void k_init_hist(const float* __restrict__ ue, const float* __restrict__ ee,
                            const int* __restrict__ rows) {
    int i = blockIdx.x * blockDim.x + threadIdx.x;   // over NN*16 = 3.2M
    if (i < NN * 16) {
        int n = i >> 4, c = i & 15;
        float4 v = (n < N_USERS)
            ? ((const float4*)ue)[(size_t)n * 16 + c]
            : ((const float4*)ee)[(size_t)(n - N_USERS) * 16 + c];
        ((float4*)g_ego)[i] = v;
        ((float4*)(g_all + (size_t)n * TOT))[c] = v;
    }
    if (i < NE) atomicAdd(&g_deg[rows[i]], 1);
}

// Launch 1: rowptr by atomic allocation (order-free; rows only need contiguity)
__global__ void k_alloc() {
    int n = blockIdx.x * blockDim.x + threadIdx.x;
    if (n >= NN) return;
    int d  = g_deg[n];
    int rp = atomicAdd(&g_total, d);
    g_rowptr[n] = rp;
    g_off[n]    = rp;
}

// Launch 2: scatter edges into CSR slots
__global__ void k_place(const int* __restrict__ rows, const int* __restrict__ cols,
                        const float* __restrict__ vals) {
    int e = blockIdx.x * blockDim.x + threadIdx.x;
    if (e >= NE) return;
    int r = rows[e];
    int p = atomicAdd(&g_off[r], 1);
    g_edge[p] = make_int2(cols[e], __float_as_int(vals[e]));
}

// ---------------------------------------------------------------------------
// Launches 3-5: fused side-gather + GC/BI transform + l2norm.
// 8 warps/block, weights + node tiles in dynamic smem (48KB for layer 0).
// Gather: warp per node, header double-buffer + shfl broadcast, 2-way unroll.
// Matmul: node-tiled (NT=4) + packed FFMA2; lanes 0-15 GC, 16-31 BI.
template<int DIN, int DOUT, int OFF>
__global__ void __launch_bounds__(256, 4)
k_layer(const float* __restrict__ Wg, const float* __restrict__ bg,
        const float* __restrict__ Wb, const float* __restrict__ bb,
        const float* __restrict__ src, float* __restrict__ dst) {
    constexpr int VE  = DIN / 32;       // floats per lane (2 or 1)
    constexpr int LPM = DOUT / 4;       // active lanes per matrix
    constexpr int NT  = 4;              // nodes per warp per matmul pass
    constexpr int WPB = 8;
    extern __shared__ __align__(16) float sdyn[];
    float* sW = sdyn;                                   // 2*DIN*DOUT
    typedef float SxTile[NT][2][DIN];
    SxTile* sx = reinterpret_cast<SxTile*>(sdyn + 2 * DIN * DOUT);  // [WPB]
    __shared__ __align__(16) float sB[2 * DOUT];

    int tid = threadIdx.x;
    for (int i = tid; i < DIN * DOUT; i += blockDim.x) { sW[i] = Wg[i]; sW[DIN * DOUT + i] = Wb[i]; }
    for (int i = tid; i < DOUT; i += blockDim.x)       { sB[i] = bg[i]; sB[DOUT + i] = bb[i]; }
    __syncthreads();

    int w = tid >> 5, lane = tid & 31;
    int h  = lane >> 4;                 // 0 = GC, 1 = BI
    int jl = lane & 15;
    int jc = (jl < LPM) ? jl : 0;
    const float* wbase = sW + h * DIN * DOUT;

    for (int nb = (blockIdx.x * WPB + w) * NT; nb < NN; nb += gridDim.x * WPB * NT) {
        // ---- gather NT nodes into sx ----
        #pragma unroll
        for (int t = 0; t < NT; t++) {
            int n = nb + t;
            if (n >= NN) break;
            float er[VE], a0[VE], a1[VE];
            #pragma unroll
            for (int c = 0; c < VE; c++) {
                er[c] = src[(size_t)n * DIN + VE * lane + c];
                a0[c] = 0.f; a1[c] = 0.f;
            }
            int s0 = g_rowptr[n], cnt = g_deg[n];
            int2 ev = make_int2(0, 0);
            if (lane < cnt) ev = g_edge[s0 + lane];
            for (int base = 0; base < cnt; base += 32) {
                int2 evn = make_int2(0, 0);
                int nx = base + 32 + lane;
                if (nx < cnt) evn = g_edge[s0 + nx];
                int vn2 = (min(32, cnt - base) + 1) & ~1;
                for (int m = 0; m < vn2; m += 2) {
                    int   c0 = __shfl_sync(0xffffffffu, ev.x, m);
                    float v0 = __int_as_float(__shfl_sync(0xffffffffu, ev.y, m));
                    int   c1 = __shfl_sync(0xffffffffu, ev.x, m + 1);
                    float v1 = __int_as_float(__shfl_sync(0xffffffffu, ev.y, m + 1));
                    const float* r0 = src + (size_t)c0 * DIN + VE * lane;
                    const float* r1 = src + (size_t)c1 * DIN + VE * lane;
                    if (VE == 2) {
                        float2 x0 = *(const float2*)r0;
                        float2 x1 = *(const float2*)r1;
                        a0[0] = fmaf(v0, x0.x, a0[0]);
                        a0[1] = fmaf(v0, x0.y, a0[1]);
                        a1[0] = fmaf(v1, x1.x, a1[0]);
                        a1[1] = fmaf(v1, x1.y, a1[1]);
                    } else {
                        a0[0] = fmaf(v0, r0[0], a0[0]);
                        a1[0] = fmaf(v1, r1[0], a1[0]);
                    }
                }
                ev = evn;
            }
            #pragma unroll
            for (int c = 0; c < VE; c++) {
                float acc = a0[c] + a1[c];
                int k = VE * lane + c;
                sx[w][t][0][k] = er[c] + acc;
                sx[w][t][1][k] = er[c] * acc;
            }
        }
        __syncwarp();

        // ---- node-tiled matmul with packed FFMA2 ----
        unsigned long long p01[NT], p23[NT];
        #pragma unroll
        for (int t = 0; t < NT; t++) { p01[t] = 0ull; p23[t] = 0ull; }

        #pragma unroll
        for (int k4 = 0; k4 < DIN; k4 += 4) {
            float4 xv[NT];
            #pragma unroll
            for (int t = 0; t < NT; t++)
                xv[t] = *(const float4*)(&sx[w][t][h][k4]);
            #pragma unroll
            for (int i = 0; i < 4; i++) {
                ulonglong2 wv = ((const ulonglong2*)(wbase + (k4 + i) * DOUT))[jc];
                #pragma unroll
                for (int t = 0; t < NT; t++) {
                    unsigned long long xx = pk2((&xv[t].x)[i]);
                    ffma2(p01[t], xx, wv.x);
                    ffma2(p23[t], xx, wv.y);
                }
            }
        }

        float4 bv = ((const float4*)(sB + h * DOUT))[jc];
        #pragma unroll
        for (int t = 0; t < NT; t++) {
            int n = nb + t;
            float2 a01 = upk2(p01[t]), a23 = upk2(p23[t]);
            float4 v;
            v.x = a01.x + bv.x; v.x = v.x > 0.f ? v.x : 0.01f * v.x;
            v.y = a01.y + bv.y; v.y = v.y > 0.f ? v.y : 0.01f * v.y;
            v.z = a23.x + bv.z; v.z = v.z > 0.f ? v.z : 0.01f * v.z;
            v.w = a23.y + bv.w; v.w = v.w > 0.f ? v.w : 0.01f * v.w;
            float4 o;
            o.x = v.x + __shfl_xor_sync(0xffffffffu, v.x, 16);
            o.y = v.y + __shfl_xor_sync(0xffffffffu, v.y, 16);
            o.z = v.z + __shfl_xor_sync(0xffffffffu, v.z, 16);
            o.w = v.w + __shfl_xor_sync(0xffffffffu, v.w, 16);
            float ss = o.x * o.x + o.y * o.y + o.z * o.z + o.w * o.w;
            #pragma unroll
            for (int off = LPM / 2; off > 0; off >>= 1)
                ss += __shfl_xor_sync(0xffffffffu, ss, off);
            float inv = 1.0f / fmaxf(sqrtf(ss), 1e-12f);
            if (n < NN && h == 0 && jl < LPM) {
                ((float4*)(dst + (size_t)n * DOUT))[jl] = o;
                float4 on = make_float4(o.x * inv, o.y * inv, o.z * inv, o.w * inv);
                ((float4*)(g_all + (size_t)n * TOT + OFF))[jl] = on;
            }
        }
        __syncwarp();
    }
}

// ---------------------------------------------------------------------------
// Launch 6: scoring + reset g_deg/g_total for the next call (grid covers NN).
__global__ void k_score(const int* __restrict__ users, const int* __restrict__ pos,
                        const int* __restrict__ neg, float* __restrict__ out) {
    int gi = blockIdx.x * blockDim.x + threadIdx.x;
    if (gi < NN) g_deg[gi] = 0;
    if (gi == 0) g_total = 0;

    int wid  = gi >> 5;
    int lane = threadIdx.x & 31;
    if (wid >= NB) return;
    const float* u = g_all + (size_t)users[wid] * TOT;
    const float* p = g_all + (size_t)(N_USERS + pos[wid]) * TOT;
    const float* q = g_all + (size_t)(N_USERS + neg[wid]) * TOT;
    float sp = 0.f, sn = 0.f;
    #pragma unroll
    for (int k = lane; k < TOT; k += 32) {
        float uv = u[k];
        sp += uv * p[k];
        sn += uv * q[k];
    }
    #pragma unroll
    for (int o = 16; o > 0; o >>= 1) {
        sp += __shfl_xor_sync(0xffffffffu, sp, o);
        sn += __shfl_xor_sync(0xffffffffu, sn, o);
    }
    if (lane == 0) { out[2 * wid] = sp; out[2 * wid + 1] = sn; }
}

// ---------------------------------------------------------------------------
extern "C" void kernel_launch(void* const* d_in, const int* in_sizes, int n_in,
                              void* d_out, int out_size) {
    const int*   users = (const int*)  d_in[0];
    const int*   pos   = (const int*)  d_in[1];
    const int*   neg   = (const int*)  d_in[2];
    const int*   rows  = (const int*)  d_in[3];
    const int*   cols  = (const int*)  d_in[4];
    const float* vals  = (const float*)d_in[5];
    const float* ue    = (const float*)d_in[6];
    const float* ee    = (const float*)d_in[7];
    const float* W[3][4];
    for (int l = 0; l < 3; l++)
        for (int j = 0; j < 4; j++)
            W[l][j] = (const float*)d_in[8 + 4 * l + j];

    float *p_ego, *p_ego2;
    cudaGetSymbolAddress((void**)&p_ego,  g_ego);
    cudaGetSymbolAddress((void**)&p_ego2, g_ego2);

    const int TB  = 256;
    const int TBL = 256;   // 8 warps per block for k_layer
    const int GL  = 592;   // 4 blocks/SM * 148 SMs

    // dynamic smem sizes: weights (2*DIN*DOUT) + node tiles (WPB*NT*2*DIN)
    const int SM0 = (2 * 64 * 64 + 8 * 4 * 2 * 64) * 4;   // 49152
    const int SM1 = (2 * 64 * 32 + 8 * 4 * 2 * 64) * 4;   // 32768
    const int SM2 = (2 * 32 * 16 + 8 * 4 * 2 * 32) * 4;   // 12288
    cudaFuncSetAttribute(k_layer<64, 64,  64>, cudaFuncAttributeMaxDynamicSharedMemorySize, SM0);
    cudaFuncSetAttribute(k_layer<64, 32, 128>, cudaFuncAttributeMaxDynamicSharedMemorySize, SM1);
    cudaFuncSetAttribute(k_layer<32, 16, 160>, cudaFuncAttributeMaxDynamicSharedMemorySize, SM2);

    // 0: init + histogram
    k_init_hist<<<(NN * 16 + TB - 1) / TB, TB>>>(ue, ee, rows);
    // 1: rowptr by atomic allocation
    k_alloc<<<(NN + TB - 1) / TB, TB>>>();
    // 2: CSR placement
    k_place<<<(NE + TB - 1) / TB, TB>>>(rows, cols, vals);

    // 3-5: fused layers  (launch index 3 = ncu capture slot)
    k_layer<64, 64,  64><<<GL, TBL, SM0>>>(W[0][0], W[0][1], W[0][2], W[0][3], p_ego,  p_ego2);
    k_layer<64, 32, 128><<<GL, TBL, SM1>>>(W[1][0], W[1][1], W[1][2], W[1][3], p_ego2, p_ego);
    k_layer<32, 16, 160><<<GL, TBL, SM2>>>(W[2][0], W[2][1], W[2][2], W[2][3], p_ego,  p_ego2);

    // 6: score + scratch reset
    k_score<<<(NB * 32 + TB - 1) / TB, TB>>>(users, pos, neg, (float*)d_out);
}